// round 1
// baseline (speedup 1.0000x reference)
#include <cuda_runtime.h>
#include <cuda_bf16.h>
#include <cstdint>

// Problem constants
#define BATCH 64
#define CIN   2304
#define DCH   512
#define HH    14
#define WW    14
#define HWP   196                  // 14*14
#define NTOT  (BATCH * HWP)        // 12544
#define CHW   (DCH * HWP)          // 100352

// GEMM tiling
#define BM 128
#define BN 128
#define BK 16

// ---------------- scratch (static device memory; no allocation) ----------------
__device__ float g_xr  [BATCH * CHW];
__device__ float g_q   [BATCH * CHW];
__device__ float g_k   [BATCH * CHW];
__device__ float g_v   [BATCH * CHW];
__device__ float g_att [BATCH * BATCH * HWP];
__device__ float g_virt[BATCH * CHW];
__device__ float g_co  [BATCH * CHW];
__device__ float g_stats[2 * BATCH];

// ---------------- packed fp32x2 helpers ----------------
__device__ __forceinline__ unsigned long long pack2(float a) {
    unsigned long long r;
    asm("mov.b64 %0, {%1, %1};" : "=l"(r) : "f"(a));
    return r;
}
__device__ __forceinline__ void fma2(unsigned long long& d, unsigned long long a, unsigned long long b) {
    asm("fma.rn.f32x2 %0, %1, %2, %0;" : "+l"(d) : "l"(a), "l"(b));
}
__device__ __forceinline__ float2 unpack2(unsigned long long v) {
    float2 f;
    asm("mov.b64 {%0, %1}, %2;" : "=f"(f.x), "=f"(f.y) : "l"(v));
    return f;
}

// ---------------- GEMM: C[m,n] = sum_k A[m,k] * B[k,n] ----------------
// MODE 0: 1x1 reduce.  K = 2304.  W row-major (512 x 2304).
//         B(k,n) = X[(b*2304 + k)*196 + p], n = b*196 + p.
// MODE 1: implicit 3x3 SAME conv. K = 4608 ordered k = kk*512 + c (kk = tap 0..8).
//         A(m,k) = W[(m*512 + c)*9 + kk]
//         B(k,n) = in-bounds ? X[b*100352 + c*196 + p + dy*14 + dx] : 0
// Output: O[(b*512 + m)*196 + p]
template<int MODE>
__global__ __launch_bounds__(256, 2)
void gemm_kernel(const float* __restrict__ W, const float* __restrict__ X, float* __restrict__ O)
{
    const int KDIM = (MODE == 0) ? CIN : (DCH * 9);
    const int m0 = blockIdx.y * BM;
    const int n0 = blockIdx.x * BN;
    const int t  = threadIdx.x;

    __shared__ float As[2][BK][BM + 4];   // +4 pad: 16B-aligned rows, reduced store conflicts
    __shared__ float Bs[2][BK][BN];

    // B-tile mapping: each thread owns one column n, 8 k-rows
    const int nloc = t & 127;
    const int n    = n0 + nloc;
    const int krB  = (t >> 7) * 8;       // 0 or 8
    const int b    = n / HWP;
    const int p    = n - b * HWP;
    const int py   = p / WW;
    const int px   = p - py * WW;
    const int xbase = b * ((MODE == 0) ? CIN : DCH) * HWP + p;

    // A-tile mapping: each thread owns one k-col, 8 m-rows
    const int kcA = t & 15;
    const int mA  = (t >> 4) * 8;

    float rA[8], rB[8];

    unsigned long long acc[8][4];
#pragma unroll
    for (int i = 0; i < 8; i++)
#pragma unroll
        for (int j = 0; j < 4; j++) acc[i][j] = 0ull;

    const int nk = KDIM / BK;

    // ---- load tile kt into registers ----
    auto loadRegs = [&](int kt) {
        const int k0 = kt * BK;
        if (MODE == 0) {
#pragma unroll
            for (int i = 0; i < 8; i++)
                rA[i] = W[(m0 + mA + i) * CIN + k0 + kcA];
#pragma unroll
            for (int i = 0; i < 8; i++)
                rB[i] = X[xbase + (k0 + krB + i) * HWP];
        } else {
            const int kk = k0 >> 9;          // 3x3 tap index (constant per tile)
            const int c0 = k0 & 511;
#pragma unroll
            for (int i = 0; i < 8; i++)
                rA[i] = W[((m0 + mA + i) * DCH + c0 + kcA) * 9 + kk];
            const int dy = kk / 3 - 1;
            const int dx = kk - (kk / 3) * 3 - 1;
            const bool ok = ((unsigned)(py + dy) < (unsigned)HH) && ((unsigned)(px + dx) < (unsigned)WW);
            const int off = xbase + dy * WW + dx;
#pragma unroll
            for (int i = 0; i < 8; i++) {
                float v = 0.0f;
                if (ok) v = X[off + (c0 + krB + i) * HWP];
                rB[i] = v;
            }
        }
    };
    auto storeSmem = [&](int s) {
#pragma unroll
        for (int i = 0; i < 8; i++) As[s][kcA][mA + i] = rA[i];
#pragma unroll
        for (int i = 0; i < 8; i++) Bs[s][krB + i][nloc] = rB[i];
    };

    loadRegs(0);
    storeSmem(0);
    __syncthreads();

    const int ty = t >> 4;   // m micro-tile
    const int tx = t & 15;   // n micro-tile
    int s = 0;

    for (int kt = 0; kt < nk; ++kt) {
        if (kt + 1 < nk) loadRegs(kt + 1);
#pragma unroll
        for (int kk = 0; kk < BK; ++kk) {
            float4 a0 = *(const float4*)&As[s][kk][ty * 8];
            float4 a1 = *(const float4*)&As[s][kk][ty * 8 + 4];
            float4 b0 = *(const float4*)&Bs[s][kk][tx * 8];
            float4 b1 = *(const float4*)&Bs[s][kk][tx * 8 + 4];
            unsigned long long bp[4];
            bp[0] = ((const unsigned long long*)&b0)[0];
            bp[1] = ((const unsigned long long*)&b0)[1];
            bp[2] = ((const unsigned long long*)&b1)[0];
            bp[3] = ((const unsigned long long*)&b1)[1];
            float av[8] = {a0.x, a0.y, a0.z, a0.w, a1.x, a1.y, a1.z, a1.w};
#pragma unroll
            for (int im = 0; im < 8; im++) {
                unsigned long long ap = pack2(av[im]);
#pragma unroll
                for (int jn = 0; jn < 4; jn++) fma2(acc[im][jn], ap, bp[jn]);
            }
        }
        if (kt + 1 < nk) storeSmem(s ^ 1);
        __syncthreads();
        s ^= 1;
    }

    // ---- epilogue: scatter to NCHW ----
#pragma unroll
    for (int jn = 0; jn < 8; jn++) {
        const int nn = n0 + tx * 8 + jn;
        const int bb = nn / HWP;
        const int pp = nn - bb * HWP;
        float* orow = O + bb * CHW + pp;
#pragma unroll
        for (int im = 0; im < 8; im++) {
            float2 fv = unpack2(acc[im][jn >> 1]);
            float val = (jn & 1) ? fv.y : fv.x;
            orow[(m0 + ty * 8 + im) * HWP] = val;
        }
    }
}

// ---------------- attention scores: att[i,j,p] = <q_i, k_j>_c(p) / sqrt(512) ----------------
__global__ __launch_bounds__(256)
void attn_scores(const float* __restrict__ Q, const float* __restrict__ Kin, float* __restrict__ A)
{
    const int p = blockIdx.x;
    const int t = threadIdx.x;
    __shared__ float qs[64][33];
    __shared__ float ks[64][33];

    float acc[4][4];
#pragma unroll
    for (int a = 0; a < 4; a++)
#pragma unroll
        for (int b4 = 0; b4 < 4; b4++) acc[a][b4] = 0.0f;

    const int ti = (t & 15) * 4;
    const int tj = (t >> 4) * 4;

    for (int ch = 0; ch < 16; ++ch) {
        const int c0 = ch * 32;
        __syncthreads();
        for (int e = t; e < 64 * 32; e += 256) {
            const int i = e >> 5, c = e & 31;
            qs[i][c] = Q[(i * DCH + c0 + c) * HWP + p];
            ks[i][c] = Kin[(i * DCH + c0 + c) * HWP + p];
        }
        __syncthreads();
#pragma unroll 8
        for (int c = 0; c < 32; ++c) {
            float qa[4], kb[4];
#pragma unroll
            for (int a = 0; a < 4; a++) qa[a] = qs[ti + a][c];
#pragma unroll
            for (int b4 = 0; b4 < 4; b4++) kb[b4] = ks[tj + b4][c];
#pragma unroll
            for (int a = 0; a < 4; a++)
#pragma unroll
                for (int b4 = 0; b4 < 4; b4++) acc[a][b4] = fmaf(qa[a], kb[b4], acc[a][b4]);
        }
    }
    const float scale = 0.044194173824159216f;  // 1/sqrt(512)
#pragma unroll
    for (int a = 0; a < 4; a++)
#pragma unroll
        for (int b4 = 0; b4 < 4; b4++)
            A[((ti + a) * 64 + (tj + b4)) * HWP + p] = acc[a][b4] * scale;
}

// ---------------- softmax over j for each (i, p): one warp per row ----------------
__global__ __launch_bounds__(256)
void softmax_j(float* __restrict__ A)
{
    const int gw   = (blockIdx.x * blockDim.x + threadIdx.x) >> 5;
    const int lane = threadIdx.x & 31;
    if (gw >= BATCH * HWP) return;
    const int i = gw / HWP;
    const int p = gw - i * HWP;

    const int base = i * 64 * HWP + p;
    float v0 = A[base + lane * HWP];
    float v1 = A[base + (32 + lane) * HWP];
    float m = fmaxf(v0, v1);
#pragma unroll
    for (int o = 16; o > 0; o >>= 1) m = fmaxf(m, __shfl_xor_sync(0xffffffffu, m, o));
    float e0 = __expf(v0 - m);
    float e1 = __expf(v1 - m);
    float ssum = e0 + e1;
#pragma unroll
    for (int o = 16; o > 0; o >>= 1) ssum += __shfl_xor_sync(0xffffffffu, ssum, o);
    const float inv = 1.0f / ssum;
    A[base + lane * HWP]        = e0 * inv;
    A[base + (32 + lane) * HWP] = e1 * inv;
}

// ---------------- virt[i,c,p] = sum_j att[i,j,p] * v[j,c,p] ----------------
__global__ __launch_bounds__(256)
void attn_apply(const float* __restrict__ A, const float* __restrict__ V, float* __restrict__ Out)
{
    const int p = blockIdx.x;
    const int t = threadIdx.x;
    __shared__ float as[64][65];
    __shared__ float vs[64][33];

    for (int e = t; e < 64 * 64; e += 256) {
        const int i = e >> 6, j = e & 63;
        as[i][j] = A[(i * 64 + j) * HWP + p];
    }
    __syncthreads();

    const int ti = (t & 15) * 4;
    const int tc = (t >> 4) * 2;

    for (int ch = 0; ch < 16; ++ch) {
        const int c0 = ch * 32;
        if (ch) __syncthreads();
        for (int e = t; e < 64 * 32; e += 256) {
            const int j = e >> 5, c = e & 31;
            vs[j][c] = V[(j * DCH + c0 + c) * HWP + p];
        }
        __syncthreads();
        float acc[4][2];
#pragma unroll
        for (int a = 0; a < 4; a++) { acc[a][0] = 0.0f; acc[a][1] = 0.0f; }
#pragma unroll 8
        for (int j = 0; j < 64; ++j) {
            float vv0 = vs[j][tc];
            float vv1 = vs[j][tc + 1];
#pragma unroll
            for (int a = 0; a < 4; a++) {
                const float av = as[ti + a][j];
                acc[a][0] = fmaf(av, vv0, acc[a][0]);
                acc[a][1] = fmaf(av, vv1, acc[a][1]);
            }
        }
#pragma unroll
        for (int a = 0; a < 4; a++) {
            Out[((ti + a) * DCH + c0 + tc)     * HWP + p] = acc[a][0];
            Out[((ti + a) * DCH + c0 + tc + 1) * HWP + p] = acc[a][1];
        }
    }
}

// ---------------- GroupNorm(1) stats per batch ----------------
__global__ __launch_bounds__(256)
void gn_stats(const float* __restrict__ Vt, float* __restrict__ stats)
{
    const int i = blockIdx.x;
    const int t = threadIdx.x;
    float s = 0.0f, s2 = 0.0f;
    const float* row = Vt + i * CHW;
    for (int e = t; e < CHW; e += 256) {
        const float v = row[e];
        s += v;
        s2 = fmaf(v, v, s2);
    }
    __shared__ float sh1[256];
    __shared__ float sh2[256];
    sh1[t] = s; sh2[t] = s2;
    __syncthreads();
    for (int st = 128; st > 0; st >>= 1) {
        if (t < st) { sh1[t] += sh1[t + st]; sh2[t] += sh2[t + st]; }
        __syncthreads();
    }
    if (t == 0) {
        const float inv_n = 1.0f / (float)CHW;
        const float mean = sh1[0] * inv_n;
        const float var  = sh2[0] * inv_n - mean * mean;
        stats[2 * i]     = mean;
        stats[2 * i + 1] = rsqrtf(var + 1e-5f);
    }
}

// ---------------- normalize + affine + relu (in place) ----------------
__global__ __launch_bounds__(256)
void gn_norm(float* __restrict__ Vt, const float* __restrict__ stats,
             const float* __restrict__ gamma, const float* __restrict__ beta)
{
    const int idx = blockIdx.x * 256 + threadIdx.x;
    if (idx >= BATCH * CHW) return;
    const int i = idx / CHW;
    const int c = (idx - i * CHW) / HWP;
    const float mean = stats[2 * i];
    const float rstd = stats[2 * i + 1];
    float v = (Vt[idx] - mean) * rstd * gamma[c] + beta[c];
    Vt[idx] = fmaxf(v, 0.0f);
}

// ---------------- residual + global avg pool + linear head ----------------
__global__ __launch_bounds__(256)
void pool_pred(const float* __restrict__ XR, const float* __restrict__ CO,
               const float* __restrict__ Wp, float* __restrict__ out)
{
    const int b = blockIdx.x;
    const int t = threadIdx.x;
    float acc = 0.0f;
    const float* xrow = XR + b * CHW;
    const float* crow = CO + b * CHW;
    for (int e = t; e < CHW; e += 256) {
        const int d = e / HWP;
        acc = fmaf(Wp[d], xrow[e] + crow[e], acc);
    }
    __shared__ float sh[256];
    sh[t] = acc;
    __syncthreads();
    for (int st = 128; st > 0; st >>= 1) {
        if (t < st) sh[t] += sh[t + st];
        __syncthreads();
    }
    if (t == 0) out[b] = sh[0] * (1.0f / (float)HWP);
}

// ---------------- launcher ----------------
extern "C" void kernel_launch(void* const* d_in, const int* in_sizes, int n_in,
                              void* d_out, int out_size)
{
    const float* x        = (const float*)d_in[0];
    const float* w_reduce = (const float*)d_in[1];
    const float* w_q      = (const float*)d_in[2];
    const float* w_k      = (const float*)d_in[3];
    const float* w_v      = (const float*)d_in[4];
    const float* w_conv   = (const float*)d_in[5];
    const float* gamma    = (const float*)d_in[6];
    const float* beta     = (const float*)d_in[7];
    const float* w_pred   = (const float*)d_in[8];
    float* out = (float*)d_out;

    float *xr, *q, *k, *v, *att, *virt, *co, *stats;
    cudaGetSymbolAddress((void**)&xr,    g_xr);
    cudaGetSymbolAddress((void**)&q,     g_q);
    cudaGetSymbolAddress((void**)&k,     g_k);
    cudaGetSymbolAddress((void**)&v,     g_v);
    cudaGetSymbolAddress((void**)&att,   g_att);
    cudaGetSymbolAddress((void**)&virt,  g_virt);
    cudaGetSymbolAddress((void**)&co,    g_co);
    cudaGetSymbolAddress((void**)&stats, g_stats);

    dim3 gg(NTOT / BN, DCH / BM);   // (98, 4)

    gemm_kernel<0><<<gg, 256>>>(w_reduce, x, xr);
    gemm_kernel<1><<<gg, 256>>>(w_q, xr, q);
    gemm_kernel<1><<<gg, 256>>>(w_k, xr, k);
    gemm_kernel<1><<<gg, 256>>>(w_v, xr, v);

    attn_scores<<<HWP, 256>>>(q, k, att);
    {
        const int rows = BATCH * HWP;               // 12544 warps
        const int threads = rows * 32;
        softmax_j<<<(threads + 255) / 256, 256>>>(att);
    }
    attn_apply<<<HWP, 256>>>(att, v, virt);

    gn_stats<<<BATCH, 256>>>(virt, stats);
    gn_norm<<<(BATCH * CHW + 255) / 256, 256>>>(virt, stats, gamma, beta);

    gemm_kernel<1><<<gg, 256>>>(w_conv, virt, co);

    pool_pred<<<BATCH, 256>>>(xr, co, w_pred, out);
}

// round 4
// speedup vs baseline: 2.2828x; 2.2828x over previous
#include <cuda_runtime.h>
#include <cuda_bf16.h>
#include <cstdint>

// ---------------- problem constants ----------------
#define BATCH 64
#define DCH   512
#define CIN   2304
#define HWP   196
#define NTOT  (BATCH * HWP)        // 12544
#define CHW   (DCH * HWP)          // 100352
#define QO    (BATCH * CHW)        // floats per q/k/v tensor

// ---------------- scratch (static device memory) ----------------
__device__ float4 g_xT_hi [(64*196*2304)/8];
__device__ float4 g_xT_lo [(64*196*2304)/8];
__device__ float4 g_wr_hi [(512*2304)/8];
__device__ float4 g_wr_lo [(512*2304)/8];
__device__ float4 g_wqkv_hi[(3*512*4608)/8];
__device__ float4 g_wqkv_lo[(3*512*4608)/8];
__device__ float4 g_wc_hi [(512*4608)/8];
__device__ float4 g_wc_lo [(512*4608)/8];
__device__ float4 g_xr    [(BATCH*CHW)/4];
__device__ float4 g_xrT_hi[(BATCH*CHW)/8];
__device__ float4 g_xrT_lo[(BATCH*CHW)/8];
__device__ float4 g_qkv   [(3*BATCH*CHW)/4];
__device__ float4 g_att   [(BATCH*BATCH*HWP)/4];
__device__ float4 g_virt  [(BATCH*CHW)/4];
__device__ float4 g_virtT_hi[(BATCH*CHW)/8];
__device__ float4 g_virtT_lo[(BATCH*CHW)/8];
__device__ float4 g_co    [(BATCH*CHW)/4];
__device__ float  g_stats [2*BATCH];

// ---------------- helpers ----------------
__device__ __forceinline__ uint32_t smem_to_u32(const void* p) {
    uint32_t a;
    asm("{ .reg .u64 t; cvta.to.shared.u64 t, %1; cvt.u32.u64 %0, t; }" : "=r"(a) : "l"(p));
    return a;
}
#define CP_ASYNC16(dst, src, sz) \
    asm volatile("cp.async.cg.shared.global [%0], [%1], 16, %2;" \
                 :: "r"(dst), "l"(src), "r"(sz) : "memory")
#define CP_COMMIT() asm volatile("cp.async.commit_group;" ::: "memory")
#define CP_WAIT1()  asm volatile("cp.async.wait_group 1;" ::: "memory")

#define LDMATRIX_X4(r0, r1, r2, r3, addr) \
    asm volatile("ldmatrix.sync.aligned.m8n8.x4.shared.b16 {%0,%1,%2,%3}, [%4];" \
                 : "=r"(r0), "=r"(r1), "=r"(r2), "=r"(r3) : "r"(addr))

#define MMA16816(d, a0, a1, a2, a3, b0, b1) \
    asm volatile("mma.sync.aligned.m16n8k16.row.col.f32.bf16.bf16.f32 " \
                 "{%0,%1,%2,%3}, {%4,%5,%6,%7}, {%8,%9}, {%0,%1,%2,%3};" \
                 : "+f"((d)[0]), "+f"((d)[1]), "+f"((d)[2]), "+f"((d)[3]) \
                 : "r"(a0), "r"(a1), "r"(a2), "r"(a3), "r"(b0), "r"(b1))

// smem tile layout: rows of 32 bf16 (64B), 16B slots XOR-swizzled by (row>>1)&3
__device__ __forceinline__ uint32_t swz(int row, int slot) {
    return (uint32_t)row * 64u + (uint32_t)((slot ^ ((row >> 1) & 3)) << 4);
}

// ---------------- split-bf16 GEMM via mma.sync ----------------
// D[m,n] = sum_k A(m,k)*B(k,n) in fp32 via 3 bf16 passes: hi*hi + lo*hi + hi*lo.
// MODE 0: KTOT=2304, CB=2304 (1x1 reduce, B rows = xT[b*196+p][2304]).
// MODE 1: KTOT=4608 (k = tap*512 + c), CB=512; tap -> shifted row with zero fill.
// Output: fp32 NCHW; tensor index = m/512 (for fused qkv).
#define STAGE_BYTES 24576          // A 8KB + B 16KB
#define GEMM_SMEM   (3 * STAGE_BYTES)

template<int MODE>
__global__ __launch_bounds__(256)
void gemm_mma(const __nv_bfloat16* __restrict__ Ahi, const __nv_bfloat16* __restrict__ Alo,
              const __nv_bfloat16* __restrict__ Bhi, const __nv_bfloat16* __restrict__ Blo,
              float* __restrict__ O)
{
    constexpr int KTOT = MODE ? 4608 : 2304;
    constexpr int CB   = MODE ? 512  : 2304;
    constexpr int CPS  = MODE ? 144  : 72;      // 32-wide K chunks per split pass
    constexpr int TOTAL = 3 * CPS;

    extern __shared__ char smem[];
    const uint32_t sb = smem_to_u32(smem);

    const int t    = threadIdx.x;
    const int lane = t & 31;
    const int wid  = t >> 5;
    const int m0   = blockIdx.x * 128;
    const int n0   = blockIdx.y * 256;

    // ---- load assignments ----
    const int slot  = t & 3;                    // 16B slot (0..3)
    const int lrow0 = t >> 2;                   // 0..63

    // A: 2 rows per thread (lrow0, lrow0+64); element offset into A matrix
    int aoff[2];
    uint32_t adst[2];
#pragma unroll
    for (int i = 0; i < 2; i++) {
        const int r = lrow0 + 64 * i;
        aoff[i] = (m0 + r) * KTOT + slot * 8;
        adst[i] = swz(r, slot);
    }
    // B: 4 rows per thread
    int bbase[4], bpy[4], bpx[4];
    uint32_t bdst[4];
#pragma unroll
    for (int i = 0; i < 4; i++) {
        const int r = lrow0 + 64 * i;
        const int n = n0 + r;
        const int b = n / HWP;
        const int p = n - b * HWP;
        bbase[i] = n * CB;
        bpy[i] = p / 14;
        bpx[i] = p - bpy[i] * 14;
        bdst[i] = swz(r, slot);
    }

    auto issue = [&](int chunk, int buf) {
        const uint32_t sa  = sb + (uint32_t)buf * STAGE_BYTES;
        const uint32_t sbm = sa + 8192u;
        const int split = chunk / CPS;
        const int rem   = chunk - split * CPS;
        int kbase, doff, dy = 0, dx = 0;
        if (MODE) {
            const int tap = rem >> 4;
            const int c0  = (rem & 15) * 32;
            kbase = tap * 512 + c0;
            dy = tap / 3 - 1;
            dx = tap - (tap / 3) * 3 - 1;
            doff = (dy * 14 + dx) * CB + c0;
        } else {
            kbase = rem * 32;
            doff  = kbase;
        }
        const __nv_bfloat16* Ap = (split == 1) ? Alo : Ahi;
        const __nv_bfloat16* Bp = (split == 2) ? Blo : Bhi;
#pragma unroll
        for (int i = 0; i < 2; i++)
            CP_ASYNC16(sa + adst[i], Ap + aoff[i] + kbase, 16u);
#pragma unroll
        for (int i = 0; i < 4; i++) {
            uint32_t sz = 16u;
            const __nv_bfloat16* src = Bp + bbase[i] + doff + slot * 8;
            if (MODE) {
                const bool ok = ((unsigned)(bpy[i] + dy) < 14u) &&
                                ((unsigned)(bpx[i] + dx) < 14u);
                if (!ok) { sz = 0u; src = Bp; }
            }
            CP_ASYNC16(sbm + bdst[i], src, sz);
        }
        CP_COMMIT();
    };

    // ---- per-warp fragment addresses (offsets within a stage buffer) ----
    const int wm = (wid & 1) * 64;     // warp m base (local)
    const int wn = (wid >> 1) * 64;    // warp n base (local)
    uint32_t addrA[4][2], addrB[4][2];
#pragma unroll
    for (int mi = 0; mi < 4; mi++) {
        const int row = wm + mi * 16 + (lane & 15);
#pragma unroll
        for (int kh = 0; kh < 2; kh++)
            addrA[mi][kh] = swz(row, kh * 2 + (lane >> 4));
    }
#pragma unroll
    for (int nb = 0; nb < 4; nb++) {
        const int row = wn + nb * 16 + (lane & 7) + ((lane & 16) ? 8 : 0);
#pragma unroll
        for (int kh = 0; kh < 2; kh++)
            addrB[nb][kh] = swz(row, kh * 2 + ((lane >> 3) & 1));
    }

    float acc[4][8][4];
#pragma unroll
    for (int mi = 0; mi < 4; mi++)
#pragma unroll
        for (int ni = 0; ni < 8; ni++)
#pragma unroll
            for (int r = 0; r < 4; r++) acc[mi][ni][r] = 0.0f;

    issue(0, 0);
    issue(1, 1);

    for (int it = 0; it < TOTAL; ++it) {
        CP_WAIT1();
        __syncthreads();
        if (it + 2 < TOTAL) issue(it + 2, (it + 2) % 3);
        else CP_COMMIT();

        const uint32_t sa  = sb + (uint32_t)(it % 3) * STAGE_BYTES;
        const uint32_t sbm = sa + 8192u;
#pragma unroll
        for (int kh = 0; kh < 2; kh++) {
            uint32_t a[4][4], bf[8][2];
#pragma unroll
            for (int mi = 0; mi < 4; mi++)
                LDMATRIX_X4(a[mi][0], a[mi][1], a[mi][2], a[mi][3], sa + addrA[mi][kh]);
#pragma unroll
            for (int nb = 0; nb < 4; nb++) {
                uint32_t r0, r1, r2, r3;
                LDMATRIX_X4(r0, r1, r2, r3, sbm + addrB[nb][kh]);
                bf[2 * nb][0] = r0; bf[2 * nb][1] = r1;
                bf[2 * nb + 1][0] = r2; bf[2 * nb + 1][1] = r3;
            }
#pragma unroll
            for (int mi = 0; mi < 4; mi++)
#pragma unroll
                for (int ni = 0; ni < 8; ni++)
                    MMA16816(acc[mi][ni], a[mi][0], a[mi][1], a[mi][2], a[mi][3],
                             bf[ni][0], bf[ni][1]);
        }
    }

    // ---- epilogue: scatter fp32 to NCHW ----
    const int mwb = m0 + wm;
    const int nwb = n0 + wn;
#pragma unroll
    for (int mi = 0; mi < 4; mi++) {
        const int mt = mwb + mi * 16;
        const int which = mt >> 9;
        float* obase = O + (long)which * (long)QO;
#pragma unroll
        for (int ni = 0; ni < 8; ni++) {
            const int nn = nwb + ni * 8 + (lane & 3) * 2;   // even -> pair stays in-batch
            const int b = nn / HWP;
            const int p = nn - b * HWP;
            float* orow = obase + (long)b * CHW + p;
            const int r0 = (mt + (lane >> 2)) & 511;
            const int r1 = (mt + (lane >> 2) + 8) & 511;
            *(float2*)(orow + r0 * HWP) = make_float2(acc[mi][ni][0], acc[mi][ni][1]);
            *(float2*)(orow + r1 * HWP) = make_float2(acc[mi][ni][2], acc[mi][ni][3]);
        }
    }
}

// ---------------- conversion kernels ----------------
__global__ __launch_bounds__(256)
void conv_split(const float* __restrict__ in, __nv_bfloat16* __restrict__ hi,
                __nv_bfloat16* __restrict__ lo, int n)
{
    const int i = blockIdx.x * 256 + threadIdx.x;
    if (i >= n) return;
    const float v = in[i];
    const __nv_bfloat16 h = __float2bfloat16(v);
    hi[i] = h;
    lo[i] = __float2bfloat16(v - __bfloat162float(h));
}

// weights [m][c][3][3] -> [s][m][tap*512 + c] hi/lo (fused q,k,v)
__global__ __launch_bounds__(256)
void conv_wqkv(const float* __restrict__ wq, const float* __restrict__ wk,
               const float* __restrict__ wv,
               __nv_bfloat16* __restrict__ hi, __nv_bfloat16* __restrict__ lo)
{
    const int i = blockIdx.x * 256 + threadIdx.x;
    if (i >= 3 * 512 * 4608) return;
    const int s = i / (512 * 4608);
    const int r = i - s * (512 * 4608);
    const int m = r / 4608;
    const int k = r - m * 4608;
    const int kk = k >> 9;
    const int c = k & 511;
    const float* w = (s == 0) ? wq : ((s == 1) ? wk : wv);
    const float v = w[(m * 512 + c) * 9 + kk];
    const __nv_bfloat16 h = __float2bfloat16(v);
    hi[i] = h;
    lo[i] = __float2bfloat16(v - __bfloat162float(h));
}

__global__ __launch_bounds__(256)
void conv_wc(const float* __restrict__ w,
             __nv_bfloat16* __restrict__ hi, __nv_bfloat16* __restrict__ lo)
{
    const int i = blockIdx.x * 256 + threadIdx.x;
    if (i >= 512 * 4608) return;
    const int m = i / 4608;
    const int k = i - m * 4608;
    const int kk = k >> 9;
    const int c = k & 511;
    const float v = w[(m * 512 + c) * 9 + kk];
    const __nv_bfloat16 h = __float2bfloat16(v);
    hi[i] = h;
    lo[i] = __float2bfloat16(v - __bfloat162float(h));
}

// in [b][C][196] fp32 -> out [b][196][C] bf16 hi/lo (tiled transpose)
__global__ __launch_bounds__(256)
void tconv(const float* __restrict__ in, __nv_bfloat16* __restrict__ hi,
           __nv_bfloat16* __restrict__ lo, int C)
{
    __shared__ float tile[32][33];
    const int b = blockIdx.z;
    const int c0 = blockIdx.y * 32;
    const int p0 = blockIdx.x * 32;
    const int tx = threadIdx.x, ty = threadIdx.y;   // 32 x 8
    const float* src = in + ((long)b * C + c0) * HWP;
    const int p = p0 + tx;
    for (int i = ty; i < 32; i += 8)
        tile[i][tx] = (p < HWP) ? src[i * HWP + p] : 0.0f;
    __syncthreads();
    for (int i = ty; i < 32; i += 8) {
        const int pp = p0 + i;
        if (pp < HWP) {
            const float v = tile[tx][i];
            const __nv_bfloat16 h = __float2bfloat16(v);
            const long o = ((long)b * HWP + pp) * C + c0 + tx;
            hi[o] = h;
            lo[o] = __float2bfloat16(v - __bfloat162float(h));
        }
    }
}

// ---------------- attention / norm / pool (validated in R1) ----------------
__global__ __launch_bounds__(256)
void attn_scores(const float* __restrict__ Q, const float* __restrict__ Kin, float* __restrict__ A)
{
    const int p = blockIdx.x;
    const int t = threadIdx.x;
    __shared__ float qs[64][33];
    __shared__ float ks[64][33];
    float acc[4][4];
#pragma unroll
    for (int a = 0; a < 4; a++)
#pragma unroll
        for (int b4 = 0; b4 < 4; b4++) acc[a][b4] = 0.0f;
    const int ti = (t & 15) * 4;
    const int tj = (t >> 4) * 4;
    for (int ch = 0; ch < 16; ++ch) {
        const int c0 = ch * 32;
        __syncthreads();
        for (int e = t; e < 64 * 32; e += 256) {
            const int i = e >> 5, c = e & 31;
            qs[i][c] = Q[(i * DCH + c0 + c) * HWP + p];
            ks[i][c] = Kin[(i * DCH + c0 + c) * HWP + p];
        }
        __syncthreads();
#pragma unroll 8
        for (int c = 0; c < 32; ++c) {
            float qa[4], kb[4];
#pragma unroll
            for (int a = 0; a < 4; a++) qa[a] = qs[ti + a][c];
#pragma unroll
            for (int b4 = 0; b4 < 4; b4++) kb[b4] = ks[tj + b4][c];
#pragma unroll
            for (int a = 0; a < 4; a++)
#pragma unroll
                for (int b4 = 0; b4 < 4; b4++) acc[a][b4] = fmaf(qa[a], kb[b4], acc[a][b4]);
        }
    }
    const float scale = 0.044194173824159216f;
#pragma unroll
    for (int a = 0; a < 4; a++)
#pragma unroll
        for (int b4 = 0; b4 < 4; b4++)
            A[((ti + a) * 64 + (tj + b4)) * HWP + p] = acc[a][b4] * scale;
}

__global__ __launch_bounds__(256)
void softmax_j(float* __restrict__ A)
{
    const int gw   = (blockIdx.x * blockDim.x + threadIdx.x) >> 5;
    const int lane = threadIdx.x & 31;
    if (gw >= BATCH * HWP) return;
    const int i = gw / HWP;
    const int p = gw - i * HWP;
    const int base = i * 64 * HWP + p;
    float v0 = A[base + lane * HWP];
    float v1 = A[base + (32 + lane) * HWP];
    float m = fmaxf(v0, v1);
#pragma unroll
    for (int o = 16; o > 0; o >>= 1) m = fmaxf(m, __shfl_xor_sync(0xffffffffu, m, o));
    float e0 = __expf(v0 - m);
    float e1 = __expf(v1 - m);
    float ssum = e0 + e1;
#pragma unroll
    for (int o = 16; o > 0; o >>= 1) ssum += __shfl_xor_sync(0xffffffffu, ssum, o);
    const float inv = 1.0f / ssum;
    A[base + lane * HWP]        = e0 * inv;
    A[base + (32 + lane) * HWP] = e1 * inv;
}

__global__ __launch_bounds__(256)
void attn_apply(const float* __restrict__ A, const float* __restrict__ V, float* __restrict__ Out)
{
    const int p = blockIdx.x;
    const int t = threadIdx.x;
    __shared__ float as[64][65];
    __shared__ float vs[64][33];
    for (int e = t; e < 64 * 64; e += 256) {
        const int i = e >> 6, j = e & 63;
        as[i][j] = A[(i * 64 + j) * HWP + p];
    }
    __syncthreads();
    const int ti = (t & 15) * 4;
    const int tc = (t >> 4) * 2;
    for (int ch = 0; ch < 16; ++ch) {
        const int c0 = ch * 32;
        if (ch) __syncthreads();
        for (int e = t; e < 64 * 32; e += 256) {
            const int j = e >> 5, c = e & 31;
            vs[j][c] = V[(j * DCH + c0 + c) * HWP + p];
        }
        __syncthreads();
        float acc[4][2];
#pragma unroll
        for (int a = 0; a < 4; a++) { acc[a][0] = 0.0f; acc[a][1] = 0.0f; }
#pragma unroll 8
        for (int j = 0; j < 64; ++j) {
            float vv0 = vs[j][tc];
            float vv1 = vs[j][tc + 1];
#pragma unroll
            for (int a = 0; a < 4; a++) {
                const float av = as[ti + a][j];
                acc[a][0] = fmaf(av, vv0, acc[a][0]);
                acc[a][1] = fmaf(av, vv1, acc[a][1]);
            }
        }
#pragma unroll
        for (int a = 0; a < 4; a++) {
            Out[((ti + a) * DCH + c0 + tc)     * HWP + p] = acc[a][0];
            Out[((ti + a) * DCH + c0 + tc + 1) * HWP + p] = acc[a][1];
        }
    }
}

__global__ __launch_bounds__(256)
void gn_stats(const float* __restrict__ Vt, float* __restrict__ stats)
{
    const int i = blockIdx.x;
    const int t = threadIdx.x;
    float s = 0.0f, s2 = 0.0f;
    const float* row = Vt + (long)i * CHW;
    for (int e = t; e < CHW; e += 256) {
        const float v = row[e];
        s += v;
        s2 = fmaf(v, v, s2);
    }
    __shared__ float sh1[256];
    __shared__ float sh2[256];
    sh1[t] = s; sh2[t] = s2;
    __syncthreads();
    for (int st = 128; st > 0; st >>= 1) {
        if (t < st) { sh1[t] += sh1[t + st]; sh2[t] += sh2[t + st]; }
        __syncthreads();
    }
    if (t == 0) {
        const float inv_n = 1.0f / (float)CHW;
        const float mean = sh1[0] * inv_n;
        const float var  = sh2[0] * inv_n - mean * mean;
        stats[2 * i]     = mean;
        stats[2 * i + 1] = rsqrtf(var + 1e-5f);
    }
}

__global__ __launch_bounds__(256)
void gn_norm(float* __restrict__ Vt, const float* __restrict__ stats,
             const float* __restrict__ gamma, const float* __restrict__ beta)
{
    const int idx = blockIdx.x * 256 + threadIdx.x;
    if (idx >= BATCH * CHW) return;
    const int i = idx / CHW;
    const int c = (idx - i * CHW) / HWP;
    const float mean = stats[2 * i];
    const float rstd = stats[2 * i + 1];
    float v = (Vt[idx] - mean) * rstd * gamma[c] + beta[c];
    Vt[idx] = fmaxf(v, 0.0f);
}

__global__ __launch_bounds__(256)
void pool_pred(const float* __restrict__ XR, const float* __restrict__ CO,
               const float* __restrict__ Wp, float* __restrict__ out)
{
    const int b = blockIdx.x;
    const int t = threadIdx.x;
    float acc = 0.0f;
    const float* xrow = XR + (long)b * CHW;
    const float* crow = CO + (long)b * CHW;
    for (int e = t; e < CHW; e += 256) {
        const int d = e / HWP;
        acc = fmaf(Wp[d], xrow[e] + crow[e], acc);
    }
    __shared__ float sh[256];
    sh[t] = acc;
    __syncthreads();
    for (int st = 128; st > 0; st >>= 1) {
        if (t < st) sh[t] += sh[t + st];
        __syncthreads();
    }
    if (t == 0) out[b] = sh[0] * (1.0f / (float)HWP);
}

// ---------------- launcher ----------------
extern "C" void kernel_launch(void* const* d_in, const int* in_sizes, int n_in,
                              void* d_out, int out_size)
{
    const float* x        = (const float*)d_in[0];
    const float* w_reduce = (const float*)d_in[1];
    const float* w_q      = (const float*)d_in[2];
    const float* w_k      = (const float*)d_in[3];
    const float* w_v      = (const float*)d_in[4];
    const float* w_conv   = (const float*)d_in[5];
    const float* gamma    = (const float*)d_in[6];
    const float* beta     = (const float*)d_in[7];
    const float* w_pred   = (const float*)d_in[8];
    float* out = (float*)d_out;

    cudaFuncSetAttribute(gemm_mma<0>, cudaFuncAttributeMaxDynamicSharedMemorySize, GEMM_SMEM);
    cudaFuncSetAttribute(gemm_mma<1>, cudaFuncAttributeMaxDynamicSharedMemorySize, GEMM_SMEM);

    __nv_bfloat16 *xT_hi, *xT_lo, *wr_hi, *wr_lo, *wqkv_hi, *wqkv_lo, *wc_hi, *wc_lo;
    __nv_bfloat16 *xrT_hi, *xrT_lo, *vT_hi, *vT_lo;
    float *xr, *qkv, *att, *virt, *co, *stats;
    cudaGetSymbolAddress((void**)&xT_hi,   g_xT_hi);
    cudaGetSymbolAddress((void**)&xT_lo,   g_xT_lo);
    cudaGetSymbolAddress((void**)&wr_hi,   g_wr_hi);
    cudaGetSymbolAddress((void**)&wr_lo,   g_wr_lo);
    cudaGetSymbolAddress((void**)&wqkv_hi, g_wqkv_hi);
    cudaGetSymbolAddress((void**)&wqkv_lo, g_wqkv_lo);
    cudaGetSymbolAddress((void**)&wc_hi,   g_wc_hi);
    cudaGetSymbolAddress((void**)&wc_lo,   g_wc_lo);
    cudaGetSymbolAddress((void**)&xr,      g_xr);
    cudaGetSymbolAddress((void**)&xrT_hi,  g_xrT_hi);
    cudaGetSymbolAddress((void**)&xrT_lo,  g_xrT_lo);
    cudaGetSymbolAddress((void**)&qkv,     g_qkv);
    cudaGetSymbolAddress((void**)&att,     g_att);
    cudaGetSymbolAddress((void**)&virt,    g_virt);
    cudaGetSymbolAddress((void**)&vT_hi,   g_virtT_hi);
    cudaGetSymbolAddress((void**)&vT_lo,   g_virtT_lo);
    cudaGetSymbolAddress((void**)&co,      g_co);
    cudaGetSymbolAddress((void**)&stats,   g_stats);

    // weight conversions
    conv_split<<<(512 * 2304 + 255) / 256, 256>>>(w_reduce, wr_hi, wr_lo, 512 * 2304);
    conv_wqkv<<<(3 * 512 * 4608 + 255) / 256, 256>>>(w_q, w_k, w_v, wqkv_hi, wqkv_lo);
    conv_wc<<<(512 * 4608 + 255) / 256, 256>>>(w_conv, wc_hi, wc_lo);

    // x transpose-convert, then 1x1 reduce GEMM -> xr
    tconv<<<dim3(7, 72, 64), dim3(32, 8)>>>(x, xT_hi, xT_lo, CIN);
    gemm_mma<0><<<dim3(4, 49), 256, GEMM_SMEM>>>(wr_hi, wr_lo, xT_hi, xT_lo, xr);

    // xr transpose-convert, fused qkv conv GEMM
    tconv<<<dim3(7, 16, 64), dim3(32, 8)>>>(xr, xrT_hi, xrT_lo, DCH);
    gemm_mma<1><<<dim3(12, 49), 256, GEMM_SMEM>>>(wqkv_hi, wqkv_lo, xrT_hi, xrT_lo, qkv);

    const float* q = qkv;
    const float* k = qkv + (long)QO;
    const float* v = qkv + 2 * (long)QO;

    attn_scores<<<HWP, 256>>>(q, k, att);
    softmax_j<<<(BATCH * HWP * 32 + 255) / 256, 256>>>(att);
    attn_apply<<<HWP, 256>>>(att, v, virt);

    gn_stats<<<BATCH, 256>>>(virt, stats);
    gn_norm<<<(BATCH * CHW + 255) / 256, 256>>>(virt, stats, gamma, beta);

    // final conv GEMM on normalized virt
    tconv<<<dim3(7, 16, 64), dim3(32, 8)>>>(virt, vT_hi, vT_lo, DCH);
    gemm_mma<1><<<dim3(4, 49), 256, GEMM_SMEM>>>(wc_hi, wc_lo, vT_hi, vT_lo, co);

    pool_pred<<<BATCH, 256>>>(xr, co, w_pred, out);
}